// round 1
// baseline (speedup 1.0000x reference)
#include <cuda_runtime.h>

// ---------------------------------------------------------------------------
// Weighted Kabsch (batched): R,t from keypoints->pseudo alignment.
//   inputs : keypoints [B,3,N] f32, pseudo [B,3,N] f32, weight [B,1,N] f32
//   outputs: R [B,3,3] f32 followed by t [B,3] f32 (flattened, concatenated)
//
// Kernel 1: per-batch streaming reduction of 16 sums (HBM-bound, ~235MB).
// Kernel 2: per-batch 3x3 solve via Horn quaternion (fp64 Jacobi on 4x4 K).
// ---------------------------------------------------------------------------

#define MAX_B 8192
__device__ float g_part[MAX_B * 16];

// ---------------------------------------------------------------------------
// Reduction: one CTA per batch, 256 threads, float4 streaming loads.
// acc layout: [0]=sum w, [1..3]=sum w*kp, [4..6]=sum w*ps,
//             [7+i*3+j]=sum w*kp_i*ps_j
// ---------------------------------------------------------------------------
__global__ __launch_bounds__(256) void kabsch_reduce_kernel(
    const float* __restrict__ kp, const float* __restrict__ ps,
    const float* __restrict__ w, int N)
{
    const int b   = blockIdx.x;
    const int tid = threadIdx.x;
    const size_t base3 = (size_t)b * 3 * (size_t)N;
    const size_t base1 = (size_t)b * (size_t)N;

    const float4* kx = (const float4*)(kp + base3);
    const float4* ky = (const float4*)(kp + base3 + N);
    const float4* kz = (const float4*)(kp + base3 + 2 * (size_t)N);
    const float4* px = (const float4*)(ps + base3);
    const float4* py = (const float4*)(ps + base3 + N);
    const float4* pz = (const float4*)(ps + base3 + 2 * (size_t)N);
    const float4* wv = (const float4*)(w + base1);

    const int nv = N >> 2;  // N divisible by 4 (N=4096)

    float a[16];
#pragma unroll
    for (int i = 0; i < 16; i++) a[i] = 0.0f;

#define ACC_LANE(W_, KX_, KY_, KZ_, PX_, PY_, PZ_)                            \
    {                                                                          \
        float wkx = (W_) * (KX_), wky = (W_) * (KY_), wkz = (W_) * (KZ_);      \
        a[0] += (W_);                                                          \
        a[1] += wkx;  a[2] += wky;  a[3] += wkz;                               \
        a[4] += (W_) * (PX_);  a[5] += (W_) * (PY_);  a[6] += (W_) * (PZ_);    \
        a[7]  += wkx * (PX_);  a[8]  += wkx * (PY_);  a[9]  += wkx * (PZ_);    \
        a[10] += wky * (PX_);  a[11] += wky * (PY_);  a[12] += wky * (PZ_);    \
        a[13] += wkz * (PX_);  a[14] += wkz * (PY_);  a[15] += wkz * (PZ_);    \
    }

    for (int i = tid; i < nv; i += 256) {
        float4 W4 = wv[i];
        float4 KX = kx[i], KY = ky[i], KZ = kz[i];
        float4 PX = px[i], PY = py[i], PZ = pz[i];
        ACC_LANE(W4.x, KX.x, KY.x, KZ.x, PX.x, PY.x, PZ.x);
        ACC_LANE(W4.y, KX.y, KY.y, KZ.y, PX.y, PY.y, PZ.y);
        ACC_LANE(W4.z, KX.z, KY.z, KZ.z, PX.z, PY.z, PZ.z);
        ACC_LANE(W4.w, KX.w, KY.w, KZ.w, PX.w, PY.w, PZ.w);
    }
#undef ACC_LANE

    // intra-warp tree reduce all 16 accumulators
#pragma unroll
    for (int off = 16; off > 0; off >>= 1) {
#pragma unroll
        for (int i = 0; i < 16; i++)
            a[i] += __shfl_down_sync(0xffffffffu, a[i], off);
    }

    __shared__ float red[8][16];
    const int warp = tid >> 5;
    const int lane = tid & 31;
    if (lane == 0) {
#pragma unroll
        for (int i = 0; i < 16; i++) red[warp][i] = a[i];
    }
    __syncthreads();

    if (tid < 16) {
        float s = 0.0f;
#pragma unroll
        for (int k = 0; k < 8; k++) s += red[k][tid];
        g_part[(size_t)b * 16 + tid] = s;
    }
}

// ---------------------------------------------------------------------------
// Solve: one thread per batch. Horn quaternion method in fp64.
// Jacobi eigendecomposition of the 4x4 symmetric K matrix; take the
// eigenvector of the largest eigenvalue -> proper rotation R (det=+1),
// identical to the reference's reflection-corrected Kabsch rotation.
// ---------------------------------------------------------------------------
__global__ void kabsch_solve_kernel(float* __restrict__ outR,
                                    float* __restrict__ outT, int B)
{
    const int b = blockIdx.x * blockDim.x + threadIdx.x;
    if (b >= B) return;

    const float* p = &g_part[(size_t)b * 16];

    const double W = (double)p[0];
    const double invW = 1.0 / W;
    double kc[3], pc[3];
#pragma unroll
    for (int i = 0; i < 3; i++) {
        kc[i] = (double)p[1 + i] * invW;
        pc[i] = (double)p[4 + i] * invW;
    }
    // centered cross-covariance H_ij = (1/W) * sum w kp_i ps_j  -  kc_i pc_j
    double H[3][3];
#pragma unroll
    for (int i = 0; i < 3; i++)
#pragma unroll
        for (int j = 0; j < 3; j++)
            H[i][j] = (double)p[7 + i * 3 + j] * invW - kc[i] * pc[j];

    const double Sxx = H[0][0], Sxy = H[0][1], Sxz = H[0][2];
    const double Syx = H[1][0], Syy = H[1][1], Syz = H[1][2];
    const double Szx = H[2][0], Szy = H[2][1], Szz = H[2][2];

    double A[4][4];
    A[0][0] = Sxx + Syy + Szz;
    A[0][1] = Syz - Szy;  A[0][2] = Szx - Sxz;  A[0][3] = Sxy - Syx;
    A[1][1] = Sxx - Syy - Szz;
    A[1][2] = Sxy + Syx;  A[1][3] = Szx + Sxz;
    A[2][2] = -Sxx + Syy - Szz;
    A[2][3] = Syz + Szy;
    A[3][3] = -Sxx - Syy + Szz;
    A[1][0] = A[0][1]; A[2][0] = A[0][2]; A[3][0] = A[0][3];
    A[2][1] = A[1][2]; A[3][1] = A[1][3]; A[3][2] = A[2][3];

    double V[4][4];
#pragma unroll
    for (int i = 0; i < 4; i++)
#pragma unroll
        for (int j = 0; j < 4; j++)
            V[i][j] = (i == j) ? 1.0 : 0.0;

    // cyclic Jacobi, quadratic convergence: 10 sweeps is far past fp64 limit
    for (int sweep = 0; sweep < 10; sweep++) {
        double off = 0.0;
        for (int pp = 0; pp < 3; pp++)
            for (int qq = pp + 1; qq < 4; qq++)
                off += A[pp][qq] * A[pp][qq];
        if (off < 1e-26) break;

        for (int pp = 0; pp < 3; pp++) {
            for (int qq = pp + 1; qq < 4; qq++) {
                double apq = A[pp][qq];
                if (fabs(apq) < 1e-300) continue;
                double theta = (A[qq][qq] - A[pp][pp]) / (2.0 * apq);
                double t = copysign(1.0, theta) /
                           (fabs(theta) + sqrt(theta * theta + 1.0));
                double c = 1.0 / sqrt(t * t + 1.0);
                double s = t * c;
                // A <- A J  (columns pp,qq)
                for (int k = 0; k < 4; k++) {
                    double akp = A[k][pp], akq = A[k][qq];
                    A[k][pp] = c * akp - s * akq;
                    A[k][qq] = s * akp + c * akq;
                }
                // A <- J^T A  (rows pp,qq)
                for (int k = 0; k < 4; k++) {
                    double apk = A[pp][k], aqk = A[qq][k];
                    A[pp][k] = c * apk - s * aqk;
                    A[qq][k] = s * apk + c * aqk;
                }
                // V <- V J
                for (int k = 0; k < 4; k++) {
                    double vkp = V[k][pp], vkq = V[k][qq];
                    V[k][pp] = c * vkp - s * vkq;
                    V[k][qq] = s * vkp + c * vkq;
                }
            }
        }
    }

    // pick eigenvector of largest eigenvalue
    int jm = 0;
    double lm = A[0][0];
    for (int j = 1; j < 4; j++)
        if (A[j][j] > lm) { lm = A[j][j]; jm = j; }

    double q0 = V[0][jm], q1 = V[1][jm], q2 = V[2][jm], q3 = V[3][jm];
    double qn = 1.0 / sqrt(q0 * q0 + q1 * q1 + q2 * q2 + q3 * q3);
    q0 *= qn; q1 *= qn; q2 *= qn; q3 *= qn;

    // R = rotation of quaternion (q0; q1,q2,q3), maps kp-frame -> ps-frame
    double R[3][3];
    R[0][0] = q0*q0 + q1*q1 - q2*q2 - q3*q3;
    R[0][1] = 2.0 * (q1*q2 - q0*q3);
    R[0][2] = 2.0 * (q1*q3 + q0*q2);
    R[1][0] = 2.0 * (q1*q2 + q0*q3);
    R[1][1] = q0*q0 - q1*q1 + q2*q2 - q3*q3;
    R[1][2] = 2.0 * (q2*q3 - q0*q1);
    R[2][0] = 2.0 * (q1*q3 - q0*q2);
    R[2][1] = 2.0 * (q2*q3 + q0*q1);
    R[2][2] = q0*q0 - q1*q1 - q2*q2 + q3*q3;

    // t = -(R (kc - R^T pc)) = pc - R kc
    double t0 = pc[0] - (R[0][0]*kc[0] + R[0][1]*kc[1] + R[0][2]*kc[2]);
    double t1 = pc[1] - (R[1][0]*kc[0] + R[1][1]*kc[1] + R[1][2]*kc[2]);
    double t2 = pc[2] - (R[2][0]*kc[0] + R[2][1]*kc[1] + R[2][2]*kc[2]);

    float* Rout = outR + (size_t)b * 9;
#pragma unroll
    for (int i = 0; i < 3; i++)
#pragma unroll
        for (int j = 0; j < 3; j++)
            Rout[i * 3 + j] = (float)R[i][j];

    float* Tout = outT + (size_t)b * 3;
    Tout[0] = (float)t0;
    Tout[1] = (float)t1;
    Tout[2] = (float)t2;
}

// ---------------------------------------------------------------------------
extern "C" void kernel_launch(void* const* d_in, const int* in_sizes, int n_in,
                              void* d_out, int out_size)
{
    const float* kp = (const float*)d_in[0];  // keypoints [B,3,N]
    const float* ps = (const float*)d_in[1];  // pseudo    [B,3,N]
    const float* w  = (const float*)d_in[2];  // weight    [B,1,N]

    const int B = out_size / 12;              // out = R (B*9) ++ t (B*3)
    const int N = in_sizes[2] / B;            // weight has B*N elements

    float* outR = (float*)d_out;
    float* outT = outR + (size_t)B * 9;

    kabsch_reduce_kernel<<<B, 256>>>(kp, ps, w, N);
    kabsch_solve_kernel<<<(B + 127) / 128, 128>>>(outR, outT, B);
}

// round 6
// speedup vs baseline: 2.6141x; 2.6141x over previous
#include <cuda_runtime.h>

// ---------------------------------------------------------------------------
// Weighted Kabsch (batched): R,t from keypoints->pseudo alignment.
//   inputs : keypoints [B,3,N] f32, pseudo [B,3,N] f32, weight [B,1,N] f32
//   outputs: R [B,3,3] f32 followed by t [B,3] f32 (flattened, concatenated)
//
// Kernel 1: per-batch streaming reduction of 16 sums (HBM-bound, ~235MB).
// Kernel 2: per-batch 3x3 solve via Horn quaternion — fp32 Jacobi on 4x4 K
//           (R1 post-mortem: fp64 version was 113us of 150us, pure latency).
// ---------------------------------------------------------------------------

#define MAX_B 8192
__device__ float g_part[MAX_B * 16];

// ---------------------------------------------------------------------------
// Reduction: one CTA per batch, 256 threads, float4 streaming loads.
// acc layout: [0]=sum w, [1..3]=sum w*kp, [4..6]=sum w*ps,
//             [7+i*3+j]=sum w*kp_i*ps_j
// ---------------------------------------------------------------------------
__global__ __launch_bounds__(256) void kabsch_reduce_kernel(
    const float* __restrict__ kp, const float* __restrict__ ps,
    const float* __restrict__ w, int N)
{
    const int b   = blockIdx.x;
    const int tid = threadIdx.x;
    const size_t base3 = (size_t)b * 3 * (size_t)N;
    const size_t base1 = (size_t)b * (size_t)N;

    const float4* kx = (const float4*)(kp + base3);
    const float4* ky = (const float4*)(kp + base3 + N);
    const float4* kz = (const float4*)(kp + base3 + 2 * (size_t)N);
    const float4* px = (const float4*)(ps + base3);
    const float4* py = (const float4*)(ps + base3 + N);
    const float4* pz = (const float4*)(ps + base3 + 2 * (size_t)N);
    const float4* wv = (const float4*)(w + base1);

    const int nv = N >> 2;  // N divisible by 4 (N=4096)

    float a[16];
#pragma unroll
    for (int i = 0; i < 16; i++) a[i] = 0.0f;

#define ACC_LANE(W_, KX_, KY_, KZ_, PX_, PY_, PZ_)                            \
    {                                                                          \
        float wkx = (W_) * (KX_), wky = (W_) * (KY_), wkz = (W_) * (KZ_);      \
        a[0] += (W_);                                                          \
        a[1] += wkx;  a[2] += wky;  a[3] += wkz;                               \
        a[4] += (W_) * (PX_);  a[5] += (W_) * (PY_);  a[6] += (W_) * (PZ_);    \
        a[7]  += wkx * (PX_);  a[8]  += wkx * (PY_);  a[9]  += wkx * (PZ_);    \
        a[10] += wky * (PX_);  a[11] += wky * (PY_);  a[12] += wky * (PZ_);    \
        a[13] += wkz * (PX_);  a[14] += wkz * (PY_);  a[15] += wkz * (PZ_);    \
    }

    for (int i = tid; i < nv; i += 256) {
        float4 W4 = wv[i];
        float4 KX = kx[i], KY = ky[i], KZ = kz[i];
        float4 PX = px[i], PY = py[i], PZ = pz[i];
        ACC_LANE(W4.x, KX.x, KY.x, KZ.x, PX.x, PY.x, PZ.x);
        ACC_LANE(W4.y, KX.y, KY.y, KZ.y, PX.y, PY.y, PZ.y);
        ACC_LANE(W4.z, KX.z, KY.z, KZ.z, PX.z, PY.z, PZ.z);
        ACC_LANE(W4.w, KX.w, KY.w, KZ.w, PX.w, PY.w, PZ.w);
    }
#undef ACC_LANE

    // intra-warp tree reduce all 16 accumulators
#pragma unroll
    for (int off = 16; off > 0; off >>= 1) {
#pragma unroll
        for (int i = 0; i < 16; i++)
            a[i] += __shfl_down_sync(0xffffffffu, a[i], off);
    }

    __shared__ float red[8][16];
    const int warp = tid >> 5;
    const int lane = tid & 31;
    if (lane == 0) {
#pragma unroll
        for (int i = 0; i < 16; i++) red[warp][i] = a[i];
    }
    __syncthreads();

    if (tid < 16) {
        float s = 0.0f;
#pragma unroll
        for (int k = 0; k < 8; k++) s += red[k][tid];
        g_part[(size_t)b * 16 + tid] = s;
    }
}

// ---------------------------------------------------------------------------
// Solve: one thread per batch. Horn quaternion method, all fp32.
// Jacobi eigendecomposition of the 4x4 symmetric K matrix (5 unrolled
// sweeps, branch-free rotation guard); eigenvector of the largest
// eigenvalue -> proper rotation R (det=+1), identical to the reference's
// reflection-corrected Kabsch rotation.
// ---------------------------------------------------------------------------
__global__ __launch_bounds__(256) void kabsch_solve_kernel(
    float* __restrict__ outR, float* __restrict__ outT, int B)
{
    const int b = blockIdx.x * blockDim.x + threadIdx.x;
    if (b >= B) return;

    const float* p = &g_part[(size_t)b * 16];

    const float W = p[0];
    const float invW = __fdividef(1.0f, W);
    float kc[3], pc[3];
#pragma unroll
    for (int i = 0; i < 3; i++) {
        kc[i] = p[1 + i] * invW;
        pc[i] = p[4 + i] * invW;
    }
    // centered cross-covariance H_ij = (1/W) * sum w kp_i ps_j  -  kc_i pc_j
    float H[3][3];
#pragma unroll
    for (int i = 0; i < 3; i++)
#pragma unroll
        for (int j = 0; j < 3; j++)
            H[i][j] = fmaf(p[7 + i * 3 + j], invW, -kc[i] * pc[j]);

    const float Sxx = H[0][0], Sxy = H[0][1], Sxz = H[0][2];
    const float Syx = H[1][0], Syy = H[1][1], Syz = H[1][2];
    const float Szx = H[2][0], Szy = H[2][1], Szz = H[2][2];

    float A[4][4];
    A[0][0] = Sxx + Syy + Szz;
    A[0][1] = Syz - Szy;  A[0][2] = Szx - Sxz;  A[0][3] = Sxy - Syx;
    A[1][1] = Sxx - Syy - Szz;
    A[1][2] = Sxy + Syx;  A[1][3] = Szx + Sxz;
    A[2][2] = -Sxx + Syy - Szz;
    A[2][3] = Syz + Szy;
    A[3][3] = -Sxx - Syy + Szz;
    A[1][0] = A[0][1]; A[2][0] = A[0][2]; A[3][0] = A[0][3];
    A[2][1] = A[1][2]; A[3][1] = A[1][3]; A[3][2] = A[2][3];

    float V[4][4];
#pragma unroll
    for (int i = 0; i < 4; i++)
#pragma unroll
        for (int j = 0; j < 4; j++)
            V[i][j] = (i == j) ? 1.0f : 0.0f;

    // cyclic Jacobi: 5 fixed sweeps, fully unrolled, no data-dependent
    // branches (tiny pivot -> t=0 -> identity rotation).
#pragma unroll
    for (int sweep = 0; sweep < 5; sweep++) {
#pragma unroll
        for (int pp = 0; pp < 3; pp++) {
#pragma unroll
            for (int qq = pp + 1; qq < 4; qq++) {
                float apq = A[pp][qq];
                float theta = (A[qq][qq] - A[pp][pp]) * __fdividef(0.5f, apq);
                float t = copysignf(1.0f, theta) *
                          __fdividef(1.0f, fabsf(theta) +
                                     sqrtf(fmaf(theta, theta, 1.0f)));
                t = (fabsf(apq) > 1e-20f) ? t : 0.0f;
                float c = rsqrtf(fmaf(t, t, 1.0f));
                float s = t * c;
                // A <- A J  (columns pp,qq)
#pragma unroll
                for (int k = 0; k < 4; k++) {
                    float akp = A[k][pp], akq = A[k][qq];
                    A[k][pp] = c * akp - s * akq;
                    A[k][qq] = s * akp + c * akq;
                }
                // A <- J^T A  (rows pp,qq)
#pragma unroll
                for (int k = 0; k < 4; k++) {
                    float apk = A[pp][k], aqk = A[qq][k];
                    A[pp][k] = c * apk - s * aqk;
                    A[qq][k] = s * apk + c * aqk;
                }
                // V <- V J
#pragma unroll
                for (int k = 0; k < 4; k++) {
                    float vkp = V[k][pp], vkq = V[k][qq];
                    V[k][pp] = c * vkp - s * vkq;
                    V[k][qq] = s * vkp + c * vkq;
                }
            }
        }
    }

    // pick eigenvector of largest eigenvalue (branch-free selects)
    int jm = 0;
    float lm = A[0][0];
#pragma unroll
    for (int j = 1; j < 4; j++) {
        bool g = A[j][j] > lm;
        lm = g ? A[j][j] : lm;
        jm = g ? j : jm;
    }

    float q0 = V[0][jm], q1 = V[1][jm], q2 = V[2][jm], q3 = V[3][jm];
    float qn = rsqrtf(fmaf(q0, q0, fmaf(q1, q1, fmaf(q2, q2, q3 * q3))));
    q0 *= qn; q1 *= qn; q2 *= qn; q3 *= qn;

    // R = rotation of quaternion (q0; q1,q2,q3), maps kp-frame -> ps-frame
    float R[3][3];
    R[0][0] = q0*q0 + q1*q1 - q2*q2 - q3*q3;
    R[0][1] = 2.0f * (q1*q2 - q0*q3);
    R[0][2] = 2.0f * (q1*q3 + q0*q2);
    R[1][0] = 2.0f * (q1*q2 + q0*q3);
    R[1][1] = q0*q0 - q1*q1 + q2*q2 - q3*q3;
    R[1][2] = 2.0f * (q2*q3 - q0*q1);
    R[2][0] = 2.0f * (q1*q3 - q0*q2);
    R[2][1] = 2.0f * (q2*q3 + q0*q1);
    R[2][2] = q0*q0 - q1*q1 - q2*q2 + q3*q3;

    // t = -(R (kc - R^T pc)) = pc - R kc
    float t0 = pc[0] - (R[0][0]*kc[0] + R[0][1]*kc[1] + R[0][2]*kc[2]);
    float t1 = pc[1] - (R[1][0]*kc[0] + R[1][1]*kc[1] + R[1][2]*kc[2]);
    float t2 = pc[2] - (R[2][0]*kc[0] + R[2][1]*kc[1] + R[2][2]*kc[2]);

    float* Rout = outR + (size_t)b * 9;
#pragma unroll
    for (int i = 0; i < 3; i++)
#pragma unroll
        for (int j = 0; j < 3; j++)
            Rout[i * 3 + j] = R[i][j];

    float* Tout = outT + (size_t)b * 3;
    Tout[0] = t0;
    Tout[1] = t1;
    Tout[2] = t2;
}

// ---------------------------------------------------------------------------
extern "C" void kernel_launch(void* const* d_in, const int* in_sizes, int n_in,
                              void* d_out, int out_size)
{
    const float* kp = (const float*)d_in[0];  // keypoints [B,3,N]
    const float* ps = (const float*)d_in[1];  // pseudo    [B,3,N]
    const float* w  = (const float*)d_in[2];  // weight    [B,1,N]

    const int B = out_size / 12;              // out = R (B*9) ++ t (B*3)
    const int N = in_sizes[2] / B;            // weight has B*N elements

    float* outR = (float*)d_out;
    float* outT = outR + (size_t)B * 9;

    kabsch_reduce_kernel<<<B, 256>>>(kp, ps, w, N);
    kabsch_solve_kernel<<<(B + 255) / 256, 256>>>(outR, outT, B);
}